// round 1
// baseline (speedup 1.0000x reference)
#include <cuda_runtime.h>
#include <math.h>

#define MAXN 100000
#define LN_EPS 1e-5

// ---------------- scratch (static device globals; no allocation) ----------------
__device__ float  g_agg[(size_t)MAXN * 128];
__device__ float  g_h1 [(size_t)MAXN * 128];
__device__ float  g_tmp[(size_t)MAXN * 128];
__device__ float  g_cnt[MAXN];
__device__ float  g_inv[MAXN];
__device__ double g_red[8];

// ---------------- small utility kernels ----------------
__global__ void zero_f_kernel(float* __restrict__ p, long n) {
    long i = (long)blockIdx.x * blockDim.x + threadIdx.x;
    long stride = (long)gridDim.x * blockDim.x;
    for (; i < n; i += stride) p[i] = 0.0f;
}

__global__ void zero_d_kernel(double* __restrict__ p, int n) {
    int i = threadIdx.x;
    if (i < n) p[i] = 0.0;
}

__global__ void count_kernel(const int* __restrict__ dst, int E, float* __restrict__ cnt) {
    int i = blockIdx.x * blockDim.x + threadIdx.x;
    if (i < E) atomicAdd(&cnt[dst[i]], 1.0f);
}

__global__ void inv_kernel(const float* __restrict__ cnt, float* __restrict__ inv, int N) {
    int i = blockIdx.x * blockDim.x + threadIdx.x;
    if (i < N) inv[i] = 1.0f / fmaxf(cnt[i], 1.0f);
}

// ---------------- edge scatter kernels ----------------
// D=50: warp per edge, lanes 0..24 each handle a float2 (8B-aligned since row stride is 200B).
__global__ void scatter50_kernel(const float* __restrict__ x,
                                 const int* __restrict__ src,
                                 const int* __restrict__ dst,
                                 int E, float* __restrict__ agg) {
    int g = blockIdx.x * blockDim.x + threadIdx.x;
    int e = g >> 5;
    int lane = g & 31;
    if (e >= E || lane >= 25) return;
    int s = __ldg(&src[e]);
    int d = __ldg(&dst[e]);
    const float2 v = *(const float2*)(x + (size_t)s * 50 + lane * 2);
    float* p = agg + (size_t)d * 50 + lane * 2;
    asm volatile("red.global.add.v2.f32 [%0], {%1, %2};"
                 :: "l"(p), "f"(v.x), "f"(v.y) : "memory");
}

// D=128: warp per edge, lane handles one float4. Vector reduction (no return).
__global__ void scatter128_kernel(const float* __restrict__ feat,
                                  const int* __restrict__ src,
                                  const int* __restrict__ dst,
                                  int E, float* __restrict__ agg) {
    int g = blockIdx.x * blockDim.x + threadIdx.x;
    int e = g >> 5;
    int lane = g & 31;
    if (e >= E) return;
    int s = __ldg(&src[e]);
    int d = __ldg(&dst[e]);
    const float4 v = *(const float4*)(feat + (size_t)s * 128 + lane * 4);
    float* p = agg + (size_t)d * 128 + lane * 4;
    asm volatile("red.global.add.v4.f32 [%0], {%1, %2, %3, %4};"
                 :: "l"(p), "f"(v.x), "f"(v.y), "f"(v.z), "f"(v.w) : "memory");
}

// ---------------- GEMM with fused epilogues ----------------
// out[N,128] = (optional) (A1*inv_cnt) @ W1  +  A2 @ W2  [+ epilogue]
// EPI 0: + bias, store raw, accumulate (sum, sumsq) into redOut[0..1]
// EPI 1: v = prelu(ln(rawbuf)); out2 = v; out = v + acc        (skip-1 fused)
// EPI 2: v = prelu(ln(rawbuf)); out  = v + addend + acc        (skip-2 fused)
template<int Kdim, bool SCALED>
__device__ __forceinline__ void gemm_phase(const float* __restrict__ A,
                                           const float* __restrict__ W,
                                           const float* __restrict__ invc,
                                           float (&acc)[8][4],
                                           float (*sA)[16], float (*sB)[128],
                                           int tid, int rt, int ct, int blockRow, int N) {
    for (int k0 = 0; k0 < Kdim; k0 += 16) {
        // A tile [64][16]
        {
            int m = tid >> 2;
            int kkb = (tid & 3) * 4;
            int row = blockRow + m;
            float s = 1.0f;
            if (SCALED && row < N) s = invc[row];
            #pragma unroll
            for (int j = 0; j < 4; j++) {
                int k = k0 + kkb + j;
                float v = 0.0f;
                if (row < N && k < Kdim) v = A[(size_t)row * Kdim + k] * s;
                sA[m][kkb + j] = v;
            }
        }
        // W tile [16][128]
        {
            #pragma unroll
            for (int t = 0; t < 2; t++) {
                int idx = tid + t * 256;
                int kk = idx >> 5;
                int c4 = idx & 31;
                int k = k0 + kk;
                float4 v = make_float4(0.f, 0.f, 0.f, 0.f);
                if (k < Kdim) v = *(const float4*)(W + (size_t)k * 128 + c4 * 4);
                *(float4*)&sB[kk][c4 * 4] = v;
            }
        }
        __syncthreads();
        #pragma unroll
        for (int kk = 0; kk < 16; kk++) {
            float4 bv = *(float4*)&sB[kk][ct * 4];
            #pragma unroll
            for (int i = 0; i < 8; i++) {
                float a = sA[rt * 8 + i][kk];
                acc[i][0] = fmaf(a, bv.x, acc[i][0]);
                acc[i][1] = fmaf(a, bv.y, acc[i][1]);
                acc[i][2] = fmaf(a, bv.z, acc[i][2]);
                acc[i][3] = fmaf(a, bv.w, acc[i][3]);
            }
        }
        __syncthreads();
    }
}

template<int KA, int KB, int EPI>
__global__ __launch_bounds__(256)
void gemm_sage(const float* __restrict__ A1, const float* __restrict__ invc,
               const float* __restrict__ A2,
               const float* __restrict__ W1, const float* __restrict__ W2,
               const float* __restrict__ bias,
               float* __restrict__ out, float* __restrict__ out2,
               const float* __restrict__ rawbuf, const float* __restrict__ addend,
               const float* __restrict__ lnw, const float* __restrict__ lnb,
               const float* __restrict__ alpha,
               const double* __restrict__ redIn, double* __restrict__ redOut,
               int N) {
    __shared__ float sA[64][16];
    __shared__ float sB[16][128];
    __shared__ double sRed[8][2];

    int tid = threadIdx.x;
    int rt = tid >> 5;
    int ct = tid & 31;
    int blockRow = blockIdx.x * 64;

    float acc[8][4];
    #pragma unroll
    for (int i = 0; i < 8; i++)
        #pragma unroll
        for (int j = 0; j < 4; j++) acc[i][j] = 0.0f;

    if constexpr (KA > 0)
        gemm_phase<KA, true>(A1, W1, invc, acc, sA, sB, tid, rt, ct, blockRow, N);
    gemm_phase<KB, false>(A2, W2, invc, acc, sA, sB, tid, rt, ct, blockRow, N);

    int cbase = ct * 4;
    if constexpr (EPI == 0) {
        float b0 = bias[cbase], b1 = bias[cbase + 1], b2 = bias[cbase + 2], b3 = bias[cbase + 3];
        double ls = 0.0, lq = 0.0;
        #pragma unroll
        for (int i = 0; i < 8; i++) {
            int row = blockRow + rt * 8 + i;
            if (row < N) {
                float v0 = acc[i][0] + b0, v1 = acc[i][1] + b1;
                float v2 = acc[i][2] + b2, v3 = acc[i][3] + b3;
                *(float4*)&out[(size_t)row * 128 + cbase] = make_float4(v0, v1, v2, v3);
                ls += (double)v0 + (double)v1 + (double)v2 + (double)v3;
                lq += (double)v0 * v0 + (double)v1 * v1 + (double)v2 * v2 + (double)v3 * v3;
            }
        }
        #pragma unroll
        for (int off = 16; off > 0; off >>= 1) {
            ls += __shfl_down_sync(0xffffffffu, ls, off);
            lq += __shfl_down_sync(0xffffffffu, lq, off);
        }
        if (ct == 0) { sRed[rt][0] = ls; sRed[rt][1] = lq; }
        __syncthreads();
        if (tid == 0) {
            double S = 0.0, Q = 0.0;
            #pragma unroll
            for (int w = 0; w < 8; w++) { S += sRed[w][0]; Q += sRed[w][1]; }
            atomicAdd(&redOut[0], S);
            atomicAdd(&redOut[1], Q);
        }
    } else {
        double M = (double)N * 128.0;
        double mean = redIn[0] / M;
        double var = redIn[1] / M - mean * mean;
        if (var < 0.0) var = 0.0;
        float sc = (float)(1.0 / (sqrt(var) + LN_EPS));
        float mu = (float)mean;
        float a = alpha[0];
        float w0 = lnw[cbase], w1 = lnw[cbase + 1], w2 = lnw[cbase + 2], w3 = lnw[cbase + 3];
        float lb0 = lnb[cbase], lb1 = lnb[cbase + 1], lb2 = lnb[cbase + 2], lb3 = lnb[cbase + 3];
        #pragma unroll
        for (int i = 0; i < 8; i++) {
            int row = blockRow + rt * 8 + i;
            if (row < N) {
                size_t off = (size_t)row * 128 + cbase;
                float4 r = *(const float4*)&rawbuf[off];
                float v0 = (r.x - mu) * sc * w0 + lb0; v0 = v0 >= 0.f ? v0 : a * v0;
                float v1 = (r.y - mu) * sc * w1 + lb1; v1 = v1 >= 0.f ? v1 : a * v1;
                float v2 = (r.z - mu) * sc * w2 + lb2; v2 = v2 >= 0.f ? v2 : a * v2;
                float v3 = (r.w - mu) * sc * w3 + lb3; v3 = v3 >= 0.f ? v3 : a * v3;
                if constexpr (EPI == 1) {
                    *(float4*)&out2[off] = make_float4(v0, v1, v2, v3);
                    *(float4*)&out[off] = make_float4(v0 + acc[i][0], v1 + acc[i][1],
                                                      v2 + acc[i][2], v3 + acc[i][3]);
                } else {
                    float4 ad = *(const float4*)&addend[off];
                    *(float4*)&out[off] = make_float4(v0 + ad.x + acc[i][0],
                                                      v1 + ad.y + acc[i][1],
                                                      v2 + ad.z + acc[i][2],
                                                      v3 + ad.w + acc[i][3]);
                }
            }
        }
    }
}

// final LN + PReLU on the output buffer (float4 granularity)
__global__ void ln_prelu_kernel(float* __restrict__ buf, const double* __restrict__ red,
                                const float* __restrict__ lnw, const float* __restrict__ lnb,
                                const float* __restrict__ alpha, int N) {
    long idx = (long)blockIdx.x * blockDim.x + threadIdx.x;
    long total = (long)N * 32;  // N*128/4
    if (idx >= total) return;
    double M = (double)N * 128.0;
    double mean = red[0] / M;
    double var = red[1] / M - mean * mean;
    if (var < 0.0) var = 0.0;
    float sc = (float)(1.0 / (sqrt(var) + LN_EPS));
    float mu = (float)mean;
    float a = alpha[0];
    int c4 = ((int)(idx & 31)) * 4;
    float4 v = ((float4*)buf)[idx];
    float w0 = lnw[c4], w1 = lnw[c4 + 1], w2 = lnw[c4 + 2], w3 = lnw[c4 + 3];
    float b0 = lnb[c4], b1 = lnb[c4 + 1], b2 = lnb[c4 + 2], b3 = lnb[c4 + 3];
    float o0 = (v.x - mu) * sc * w0 + b0; o0 = o0 >= 0.f ? o0 : a * o0;
    float o1 = (v.y - mu) * sc * w1 + b1; o1 = o1 >= 0.f ? o1 : a * o1;
    float o2 = (v.z - mu) * sc * w2 + b2; o2 = o2 >= 0.f ? o2 : a * o2;
    float o3 = (v.w - mu) * sc * w3 + b3; o3 = o3 >= 0.f ? o3 : a * o3;
    ((float4*)buf)[idx] = make_float4(o0, o1, o2, o3);
}

// ---------------- launch ----------------
extern "C" void kernel_launch(void* const* d_in, const int* in_sizes, int n_in,
                              void* d_out, int out_size) {
    const float* x    = (const float*)d_in[0];
    const int*   srcp = (const int*)d_in[1];
    const int*   dstp = (const int*)d_in[2];
    const float* Wl1  = (const float*)d_in[3];
    const float* Wr1  = (const float*)d_in[4];
    const float* b1   = (const float*)d_in[5];
    const float* Wl2  = (const float*)d_in[6];
    const float* Wr2  = (const float*)d_in[7];
    const float* b2   = (const float*)d_in[8];
    const float* Wl3  = (const float*)d_in[9];
    const float* Wr3  = (const float*)d_in[10];
    const float* b3   = (const float*)d_in[11];
    const float* Ws1  = (const float*)d_in[12];
    const float* Ws2  = (const float*)d_in[13];
    const float* lnw1 = (const float*)d_in[14];
    const float* lnb1 = (const float*)d_in[15];
    const float* lnw2 = (const float*)d_in[16];
    const float* lnb2 = (const float*)d_in[17];
    const float* lnw3 = (const float*)d_in[18];
    const float* lnb3 = (const float*)d_in[19];
    const float* a1   = (const float*)d_in[20];
    const float* a2   = (const float*)d_in[21];
    const float* a3   = (const float*)d_in[22];

    int E = in_sizes[1];
    int N = in_sizes[0] / 50;
    long ND = (long)N * 128;

    float *agg, *h1, *tmp, *cnt, *inv;
    double* red;
    cudaGetSymbolAddress((void**)&agg, g_agg);
    cudaGetSymbolAddress((void**)&h1,  g_h1);
    cudaGetSymbolAddress((void**)&tmp, g_tmp);
    cudaGetSymbolAddress((void**)&cnt, g_cnt);
    cudaGetSymbolAddress((void**)&inv, g_inv);
    cudaGetSymbolAddress((void**)&red, g_red);

    float* out = (float*)d_out;

    int gemmGrid = (N + 63) / 64;
    int scatGrid = (int)(((long)E * 32 + 255) / 256);

    // init
    zero_d_kernel<<<1, 32>>>(red, 8);
    zero_f_kernel<<<(N + 255) / 256, 256>>>(cnt, N);
    count_kernel<<<(E + 255) / 256, 256>>>(dstp, E, cnt);
    inv_kernel<<<(N + 255) / 256, 256>>>(cnt, inv, N);

    // ---- layer 1 ----
    zero_f_kernel<<<(int)(((long)N * 50 + 255) / 256), 256>>>(agg, (long)N * 50);
    scatter50_kernel<<<scatGrid, 256>>>(x, srcp, dstp, E, agg);
    gemm_sage<50, 50, 0><<<gemmGrid, 256>>>(agg, inv, x, Wl1, Wr1, b1,
                                            h1, nullptr, nullptr, nullptr,
                                            nullptr, nullptr, nullptr,
                                            nullptr, red + 0, N);
    // h1 := prelu(ln(h1)); tmp := h1n + x@Ws1
    gemm_sage<0, 50, 1><<<gemmGrid, 256>>>(nullptr, nullptr, x, nullptr, Ws1, nullptr,
                                           tmp, h1, h1, nullptr,
                                           lnw1, lnb1, a1,
                                           red + 0, nullptr, N);

    // ---- layer 2 ----
    zero_f_kernel<<<(int)((ND + 255) / 256), 256>>>(agg, ND);
    scatter128_kernel<<<scatGrid, 256>>>(tmp, srcp, dstp, E, agg);
    gemm_sage<128, 128, 0><<<gemmGrid, 256>>>(agg, inv, tmp, Wl2, Wr2, b2,
                                              tmp, nullptr, nullptr, nullptr,
                                              nullptr, nullptr, nullptr,
                                              nullptr, red + 2, N);
    // tmp := prelu(ln(tmp)) + h1n + x@Ws2
    gemm_sage<0, 50, 2><<<gemmGrid, 256>>>(nullptr, nullptr, x, nullptr, Ws2, nullptr,
                                           tmp, nullptr, tmp, h1,
                                           lnw2, lnb2, a2,
                                           red + 2, nullptr, N);

    // ---- layer 3 ----
    zero_f_kernel<<<(int)((ND + 255) / 256), 256>>>(agg, ND);
    scatter128_kernel<<<scatGrid, 256>>>(tmp, srcp, dstp, E, agg);
    gemm_sage<128, 128, 0><<<gemmGrid, 256>>>(agg, inv, tmp, Wl3, Wr3, b3,
                                              out, nullptr, nullptr, nullptr,
                                              nullptr, nullptr, nullptr,
                                              nullptr, red + 4, N);
    ln_prelu_kernel<<<(int)(((long)N * 32 + 255) / 256), 256>>>(out, red + 4,
                                                                lnw3, lnb3, a3, N);
}

// round 3
// speedup vs baseline: 1.1270x; 1.1270x over previous
#include <cuda_runtime.h>
#include <math.h>

#define MAXN 100000
#define MAXE 1600000
#define LN_EPS 1e-5

typedef unsigned long long u64;

// ---------------- scratch (static device globals; no allocation) ----------------
__device__ float  g_agg[(size_t)MAXN * 128];
__device__ float  g_h1 [(size_t)MAXN * 128];
__device__ float  g_tmp[(size_t)MAXN * 128];
__device__ float  g_inv[MAXN];
__device__ double g_red[8];
__device__ int    g_hist[MAXN];
__device__ int    g_incl[MAXN];
__device__ int    g_rowptr[MAXN + 1];
__device__ int    g_cursor[MAXN];
__device__ int    g_blk[128];
__device__ int    g_csr[MAXE];

// ---------------- f32x2 packed helpers ----------------
__device__ __forceinline__ u64 pack2(float x) {
    u64 r; asm("mov.b64 %0, {%1, %1};" : "=l"(r) : "f"(x)); return r;
}
__device__ __forceinline__ void fma2(u64& d, u64 a, u64 b) {
    asm("fma.rn.f32x2 %0, %1, %2, %3;" : "=l"(d) : "l"(a), "l"(b), "l"(d));
}
__device__ __forceinline__ float2 unpk(u64 v) {
    float2 f; asm("mov.b64 {%0, %1}, %2;" : "=f"(f.x), "=f"(f.y) : "l"(v)); return f;
}

// ---------------- small utility kernels ----------------
__global__ void zero_d_kernel(double* __restrict__ p, int n) {
    int i = threadIdx.x; if (i < n) p[i] = 0.0;
}
__global__ void zero_i_kernel(int* __restrict__ p, int n) {
    int i = blockIdx.x * blockDim.x + threadIdx.x;
    if (i < n) p[i] = 0;
}
__global__ void hist_kernel(const int* __restrict__ dst, int E, int* __restrict__ hist) {
    int i = blockIdx.x * blockDim.x + threadIdx.x;
    if (i < E) atomicAdd(&hist[dst[i]], 1);
}

// two-level inclusive scan over hist -> rowptr
__global__ void scan1_kernel(const int* __restrict__ hist, int* __restrict__ incl,
                             int* __restrict__ blkSum, int N) {
    __shared__ int sh[1024];
    int i = blockIdx.x * 1024 + threadIdx.x;
    int v = (i < N) ? hist[i] : 0;
    sh[threadIdx.x] = v;
    __syncthreads();
    #pragma unroll
    for (int off = 1; off < 1024; off <<= 1) {
        int t = (threadIdx.x >= off) ? sh[threadIdx.x - off] : 0;
        __syncthreads();
        sh[threadIdx.x] += t;
        __syncthreads();
    }
    if (i < N) incl[i] = sh[threadIdx.x];
    if (threadIdx.x == 1023) blkSum[blockIdx.x] = sh[1023];
}
__global__ void scan2_kernel(int* __restrict__ blkSum, int nb) {
    if (threadIdx.x == 0) {
        int run = 0;
        for (int b = 0; b < nb; b++) { int t = blkSum[b]; blkSum[b] = run; run += t; }
    }
}
__global__ void scan3_kernel(const int* __restrict__ incl, const int* __restrict__ blkOff,
                             int* __restrict__ rowptr, int N) {
    int i = blockIdx.x * blockDim.x + threadIdx.x;
    if (i < N) rowptr[i + 1] = incl[i] + blkOff[i >> 10];
    if (i == 0) rowptr[0] = 0;
}
__global__ void inv_cursor_kernel(const int* __restrict__ rowptr, float* __restrict__ inv,
                                  int* __restrict__ cursor, int N) {
    int i = blockIdx.x * blockDim.x + threadIdx.x;
    if (i < N) {
        int b = rowptr[i], e = rowptr[i + 1];
        int c = e - b;
        inv[i] = 1.0f / (float)(c > 1 ? c : 1);
        cursor[i] = b;
    }
}
__global__ void fill_csr_kernel(const int* __restrict__ src, const int* __restrict__ dst,
                                int E, int* __restrict__ cursor, int* __restrict__ csr) {
    int e = blockIdx.x * blockDim.x + threadIdx.x;
    if (e < E) {
        int p = atomicAdd(&cursor[dst[e]], 1);
        csr[p] = src[e];
    }
}

// ---------------- CSR mean-aggregation (gather, no atomics) ----------------
// warp per node, lane covers one float4 of the 128-wide row
__global__ void aggregate128_kernel(const float* __restrict__ feat,
                                    const int* __restrict__ rowptr,
                                    const int* __restrict__ csr,
                                    const float* __restrict__ inv,
                                    float* __restrict__ mean, int N) {
    int warp = (blockIdx.x * blockDim.x + threadIdx.x) >> 5;
    int lane = threadIdx.x & 31;
    if (warp >= N) return;
    int beg = rowptr[warp], end = rowptr[warp + 1];
    float4 a0 = make_float4(0.f, 0.f, 0.f, 0.f);
    float4 a1 = a0, a2 = a0, a3 = a0;
    int e = beg;
    for (; e + 3 < end; e += 4) {
        int s0 = __ldg(&csr[e]);
        int s1 = __ldg(&csr[e + 1]);
        int s2 = __ldg(&csr[e + 2]);
        int s3 = __ldg(&csr[e + 3]);
        float4 v0 = *(const float4*)(feat + (size_t)s0 * 128 + lane * 4);
        float4 v1 = *(const float4*)(feat + (size_t)s1 * 128 + lane * 4);
        float4 v2 = *(const float4*)(feat + (size_t)s2 * 128 + lane * 4);
        float4 v3 = *(const float4*)(feat + (size_t)s3 * 128 + lane * 4);
        a0.x += v0.x; a0.y += v0.y; a0.z += v0.z; a0.w += v0.w;
        a1.x += v1.x; a1.y += v1.y; a1.z += v1.z; a1.w += v1.w;
        a2.x += v2.x; a2.y += v2.y; a2.z += v2.z; a2.w += v2.w;
        a3.x += v3.x; a3.y += v3.y; a3.z += v3.z; a3.w += v3.w;
    }
    for (; e < end; e++) {
        int s = __ldg(&csr[e]);
        float4 v = *(const float4*)(feat + (size_t)s * 128 + lane * 4);
        a0.x += v.x; a0.y += v.y; a0.z += v.z; a0.w += v.w;
    }
    float s = inv[warp];
    float4 r;
    r.x = (a0.x + a1.x + a2.x + a3.x) * s;
    r.y = (a0.y + a1.y + a2.y + a3.y) * s;
    r.z = (a0.z + a1.z + a2.z + a3.z) * s;
    r.w = (a0.w + a1.w + a2.w + a3.w) * s;
    *(float4*)(mean + (size_t)warp * 128 + lane * 4) = r;
}

// D=50 variant: lanes 0..24 each cover a float2
__global__ void aggregate50_kernel(const float* __restrict__ feat,
                                   const int* __restrict__ rowptr,
                                   const int* __restrict__ csr,
                                   const float* __restrict__ inv,
                                   float* __restrict__ mean, int N) {
    int warp = (blockIdx.x * blockDim.x + threadIdx.x) >> 5;
    int lane = threadIdx.x & 31;
    if (warp >= N || lane >= 25) return;
    int beg = rowptr[warp], end = rowptr[warp + 1];
    float2 a0 = make_float2(0.f, 0.f);
    float2 a1 = a0, a2 = a0, a3 = a0;
    int e = beg;
    for (; e + 3 < end; e += 4) {
        int s0 = __ldg(&csr[e]);
        int s1 = __ldg(&csr[e + 1]);
        int s2 = __ldg(&csr[e + 2]);
        int s3 = __ldg(&csr[e + 3]);
        float2 v0 = *(const float2*)(feat + (size_t)s0 * 50 + lane * 2);
        float2 v1 = *(const float2*)(feat + (size_t)s1 * 50 + lane * 2);
        float2 v2 = *(const float2*)(feat + (size_t)s2 * 50 + lane * 2);
        float2 v3 = *(const float2*)(feat + (size_t)s3 * 50 + lane * 2);
        a0.x += v0.x; a0.y += v0.y;
        a1.x += v1.x; a1.y += v1.y;
        a2.x += v2.x; a2.y += v2.y;
        a3.x += v3.x; a3.y += v3.y;
    }
    for (; e < end; e++) {
        int s = __ldg(&csr[e]);
        float2 v = *(const float2*)(feat + (size_t)s * 50 + lane * 2);
        a0.x += v.x; a0.y += v.y;
    }
    float s = inv[warp];
    float2 r;
    r.x = (a0.x + a1.x + a2.x + a3.x) * s;
    r.y = (a0.y + a1.y + a2.y + a3.y) * s;
    *(float2*)(mean + (size_t)warp * 50 + lane * 2) = r;
}

// ---------------- 128x128-tile GEMM, packed f32x2 FMA, fused epilogues ----------------
// out[N,128] = (optional) A1 @ W1 + A2 @ W2  [+ epilogue]
// EPI 0: + bias, store raw, accumulate (sum, sumsq) into redOut[0..1]
// EPI 1: v = prelu(ln(rawbuf)); out2 = v; out = v + acc        (skip-1 fused)
// EPI 2: v = prelu(ln(rawbuf)); out  = v + addend + acc        (skip-2 fused)
template<int Kdim>
__device__ __forceinline__ void gphase(const float* __restrict__ A,
                                       const float* __restrict__ W,
                                       u64 (&acc)[8][4],
                                       u64 (*sA2)[17], float (*sB)[128],
                                       int tid, int tx, int ty, int blockRow, int N) {
    for (int k0 = 0; k0 < Kdim; k0 += 16) {
        // A tile [128][16] -> pre-duplicated (a,a) u64 pairs
        #pragma unroll
        for (int t = 0; t < 8; t++) {
            int lin = tid + t * 256;
            int m = lin >> 4;
            int k = lin & 15;
            int row = blockRow + m;
            int kk = k0 + k;
            float v = 0.0f;
            if (row < N && kk < Kdim) v = A[(size_t)row * Kdim + kk];
            sA2[m][k] = pack2(v);
        }
        // W tile [16][128]
        #pragma unroll
        for (int t = 0; t < 2; t++) {
            int lin = tid + t * 256;
            int kk = lin >> 5;
            int c4 = lin & 31;
            int k = k0 + kk;
            float4 v = make_float4(0.f, 0.f, 0.f, 0.f);
            if (k < Kdim) v = *(const float4*)(W + (size_t)k * 128 + c4 * 4);
            *(float4*)&sB[kk][c4 * 4] = v;
        }
        __syncthreads();
        #pragma unroll
        for (int kk = 0; kk < 16; kk++) {
            ulonglong2 t0 = *(const ulonglong2*)&sB[kk][tx * 8];
            ulonglong2 t1 = *(const ulonglong2*)&sB[kk][tx * 8 + 4];
            u64 b0 = t0.x, b1 = t0.y, b2 = t1.x, b3 = t1.y;
            #pragma unroll
            for (int i = 0; i < 8; i++) {
                u64 a = sA2[ty * 8 + i][kk];
                fma2(acc[i][0], a, b0);
                fma2(acc[i][1], a, b1);
                fma2(acc[i][2], a, b2);
                fma2(acc[i][3], a, b3);
            }
        }
        __syncthreads();
    }
}

template<int KA, int KB, int EPI>
__global__ __launch_bounds__(256)
void gemm_sage(const float* __restrict__ A1, const float* __restrict__ A2,
               const float* __restrict__ W1, const float* __restrict__ W2,
               const float* __restrict__ bias,
               float* __restrict__ out, float* __restrict__ out2,
               const float* __restrict__ rawbuf, const float* __restrict__ addend,
               const float* __restrict__ lnw, const float* __restrict__ lnb,
               const float* __restrict__ alpha,
               const double* __restrict__ redIn, double* __restrict__ redOut,
               int N) {
    __shared__ __align__(16) u64   sA2[128][17];
    __shared__ __align__(16) float sB[16][128];
    __shared__ double sRed[8][2];

    int tid = threadIdx.x;
    int tx = tid & 15;   // col group of 8
    int ty = tid >> 4;   // row group of 8
    int blockRow = blockIdx.x * 128;

    u64 acc[8][4];
    u64 z = pack2(0.0f);
    #pragma unroll
    for (int i = 0; i < 8; i++)
        #pragma unroll
        for (int j = 0; j < 4; j++) acc[i][j] = z;

    if constexpr (KA > 0)
        gphase<KA>(A1, W1, acc, sA2, sB, tid, tx, ty, blockRow, N);
    gphase<KB>(A2, W2, acc, sA2, sB, tid, tx, ty, blockRow, N);

    int cb = tx * 8;
    if constexpr (EPI == 0) {
        float bs[8];
        #pragma unroll
        for (int j = 0; j < 8; j++) bs[j] = bias[cb + j];
        double ls = 0.0, lq = 0.0;
        #pragma unroll
        for (int i = 0; i < 8; i++) {
            int row = blockRow + ty * 8 + i;
            if (row < N) {
                float c[8];
                #pragma unroll
                for (int p = 0; p < 4; p++) {
                    float2 f = unpk(acc[i][p]);
                    c[2 * p] = f.x + bs[2 * p];
                    c[2 * p + 1] = f.y + bs[2 * p + 1];
                }
                size_t off = (size_t)row * 128 + cb;
                *(float4*)&out[off] = make_float4(c[0], c[1], c[2], c[3]);
                *(float4*)&out[off + 4] = make_float4(c[4], c[5], c[6], c[7]);
                #pragma unroll
                for (int j = 0; j < 8; j++) {
                    ls += (double)c[j];
                    lq += (double)c[j] * (double)c[j];
                }
            }
        }
        #pragma unroll
        for (int off = 16; off > 0; off >>= 1) {
            ls += __shfl_down_sync(0xffffffffu, ls, off);
            lq += __shfl_down_sync(0xffffffffu, lq, off);
        }
        int wid = tid >> 5;
        if ((tid & 31) == 0) { sRed[wid][0] = ls; sRed[wid][1] = lq; }
        __syncthreads();
        if (tid == 0) {
            double S = 0.0, Q = 0.0;
            #pragma unroll
            for (int w = 0; w < 8; w++) { S += sRed[w][0]; Q += sRed[w][1]; }
            atomicAdd(&redOut[0], S);
            atomicAdd(&redOut[1], Q);
        }
    } else {
        double M = (double)N * 128.0;
        double mean = redIn[0] / M;
        double var = redIn[1] / M - mean * mean;
        if (var < 0.0) var = 0.0;
        float sc = (float)(1.0 / (sqrt(var) + LN_EPS));
        float mu = (float)mean;
        float a = alpha[0];
        float w[8], lb[8];
        #pragma unroll
        for (int j = 0; j < 8; j++) { w[j] = lnw[cb + j]; lb[j] = lnb[cb + j]; }
        #pragma unroll
        for (int i = 0; i < 8; i++) {
            int row = blockRow + ty * 8 + i;
            if (row < N) {
                size_t off = (size_t)row * 128 + cb;
                float4 r0 = *(const float4*)&rawbuf[off];
                float4 r1 = *(const float4*)&rawbuf[off + 4];
                float rv[8] = {r0.x, r0.y, r0.z, r0.w, r1.x, r1.y, r1.z, r1.w};
                float v[8];
                #pragma unroll
                for (int j = 0; j < 8; j++) {
                    float t = (rv[j] - mu) * sc * w[j] + lb[j];
                    v[j] = t >= 0.f ? t : a * t;
                }
                float af[8];
                #pragma unroll
                for (int p = 0; p < 4; p++) {
                    float2 f = unpk(acc[i][p]);
                    af[2 * p] = f.x; af[2 * p + 1] = f.y;
                }
                if constexpr (EPI == 1) {
                    *(float4*)&out2[off] = make_float4(v[0], v[1], v[2], v[3]);
                    *(float4*)&out2[off + 4] = make_float4(v[4], v[5], v[6], v[7]);
                    *(float4*)&out[off] = make_float4(v[0] + af[0], v[1] + af[1],
                                                      v[2] + af[2], v[3] + af[3]);
                    *(float4*)&out[off + 4] = make_float4(v[4] + af[4], v[5] + af[5],
                                                          v[6] + af[6], v[7] + af[7]);
                } else {
                    float4 d0 = *(const float4*)&addend[off];
                    float4 d1 = *(const float4*)&addend[off + 4];
                    *(float4*)&out[off] = make_float4(v[0] + d0.x + af[0], v[1] + d0.y + af[1],
                                                      v[2] + d0.z + af[2], v[3] + d0.w + af[3]);
                    *(float4*)&out[off + 4] = make_float4(v[4] + d1.x + af[4], v[5] + d1.y + af[5],
                                                          v[6] + d1.z + af[6], v[7] + d1.w + af[7]);
                }
            }
        }
    }
}

// final LN + PReLU on the output buffer
__global__ void ln_prelu_kernel(float* __restrict__ buf, const double* __restrict__ red,
                                const float* __restrict__ lnw, const float* __restrict__ lnb,
                                const float* __restrict__ alpha, int N) {
    long idx = (long)blockIdx.x * blockDim.x + threadIdx.x;
    long total = (long)N * 32;
    if (idx >= total) return;
    double M = (double)N * 128.0;
    double mean = red[0] / M;
    double var = red[1] / M - mean * mean;
    if (var < 0.0) var = 0.0;
    float sc = (float)(1.0 / (sqrt(var) + LN_EPS));
    float mu = (float)mean;
    float a = alpha[0];
    int c4 = ((int)(idx & 31)) * 4;
    float4 v = ((float4*)buf)[idx];
    float w0 = lnw[c4], w1 = lnw[c4 + 1], w2 = lnw[c4 + 2], w3 = lnw[c4 + 3];
    float b0 = lnb[c4], b1 = lnb[c4 + 1], b2 = lnb[c4 + 2], b3 = lnb[c4 + 3];
    float o0 = (v.x - mu) * sc * w0 + b0; o0 = o0 >= 0.f ? o0 : a * o0;
    float o1 = (v.y - mu) * sc * w1 + b1; o1 = o1 >= 0.f ? o1 : a * o1;
    float o2 = (v.z - mu) * sc * w2 + b2; o2 = o2 >= 0.f ? o2 : a * o2;
    float o3 = (v.w - mu) * sc * w3 + b3; o3 = o3 >= 0.f ? o3 : a * o3;
    ((float4*)buf)[idx] = make_float4(o0, o1, o2, o3);
}

// ---------------- launch ----------------
extern "C" void kernel_launch(void* const* d_in, const int* in_sizes, int n_in,
                              void* d_out, int out_size) {
    const float* x    = (const float*)d_in[0];
    const int*   srcp = (const int*)d_in[1];
    const int*   dstp = (const int*)d_in[2];
    const float* Wl1  = (const float*)d_in[3];
    const float* Wr1  = (const float*)d_in[4];
    const float* b1   = (const float*)d_in[5];
    const float* Wl2  = (const float*)d_in[6];
    const float* Wr2  = (const float*)d_in[7];
    const float* b2   = (const float*)d_in[8];
    const float* Wl3  = (const float*)d_in[9];
    const float* Wr3  = (const float*)d_in[10];
    const float* b3   = (const float*)d_in[11];
    const float* Ws1  = (const float*)d_in[12];
    const float* Ws2  = (const float*)d_in[13];
    const float* lnw1 = (const float*)d_in[14];
    const float* lnb1 = (const float*)d_in[15];
    const float* lnw2 = (const float*)d_in[16];
    const float* lnb2 = (const float*)d_in[17];
    const float* lnw3 = (const float*)d_in[18];
    const float* lnb3 = (const float*)d_in[19];
    const float* a1   = (const float*)d_in[20];
    const float* a2   = (const float*)d_in[21];
    const float* a3   = (const float*)d_in[22];

    int E = in_sizes[1];
    int N = in_sizes[0] / 50;

    float *agg, *h1, *tmp, *inv;
    double* red;
    int *hist, *incl, *rowptr, *cursor, *blk, *csr;
    cudaGetSymbolAddress((void**)&agg,    g_agg);
    cudaGetSymbolAddress((void**)&h1,     g_h1);
    cudaGetSymbolAddress((void**)&tmp,    g_tmp);
    cudaGetSymbolAddress((void**)&inv,    g_inv);
    cudaGetSymbolAddress((void**)&red,    g_red);
    cudaGetSymbolAddress((void**)&hist,   g_hist);
    cudaGetSymbolAddress((void**)&incl,   g_incl);
    cudaGetSymbolAddress((void**)&rowptr, g_rowptr);
    cudaGetSymbolAddress((void**)&cursor, g_cursor);
    cudaGetSymbolAddress((void**)&blk,    g_blk);
    cudaGetSymbolAddress((void**)&csr,    g_csr);

    float* out = (float*)d_out;

    int gemmGrid = (N + 127) / 128;
    int aggGrid = (N + 7) / 8;                 // 8 warps (256 thr) per block
    int nScanBlk = (N + 1023) / 1024;

    // ---- CSR build ----
    zero_d_kernel<<<1, 32>>>(red, 8);
    zero_i_kernel<<<(N + 255) / 256, 256>>>(hist, N);
    hist_kernel<<<(E + 255) / 256, 256>>>(dstp, E, hist);
    scan1_kernel<<<nScanBlk, 1024>>>(hist, incl, blk, N);
    scan2_kernel<<<1, 32>>>(blk, nScanBlk);
    scan3_kernel<<<(N + 255) / 256, 256>>>(incl, blk, rowptr, N);
    inv_cursor_kernel<<<(N + 255) / 256, 256>>>(rowptr, inv, cursor, N);
    fill_csr_kernel<<<(E + 255) / 256, 256>>>(srcp, dstp, E, cursor, csr);

    // ---- layer 1 ----
    aggregate50_kernel<<<aggGrid, 256>>>(x, rowptr, csr, inv, agg, N);
    gemm_sage<50, 50, 0><<<gemmGrid, 256>>>(agg, x, Wl1, Wr1, b1,
                                            h1, nullptr, nullptr, nullptr,
                                            nullptr, nullptr, nullptr,
                                            nullptr, red + 0, N);
    // h1 := prelu(ln(h1)); tmp := h1n + x@Ws1
    gemm_sage<0, 50, 1><<<gemmGrid, 256>>>(nullptr, x, nullptr, Ws1, nullptr,
                                           tmp, h1, h1, nullptr,
                                           lnw1, lnb1, a1,
                                           red + 0, nullptr, N);

    // ---- layer 2 ----
    aggregate128_kernel<<<aggGrid, 256>>>(tmp, rowptr, csr, inv, agg, N);
    gemm_sage<128, 128, 0><<<gemmGrid, 256>>>(agg, tmp, Wl2, Wr2, b2,
                                              tmp, nullptr, nullptr, nullptr,
                                              nullptr, nullptr, nullptr,
                                              nullptr, red + 2, N);
    // tmp := prelu(ln(tmp)) + h1n + x@Ws2
    gemm_sage<0, 50, 2><<<gemmGrid, 256>>>(nullptr, x, nullptr, Ws2, nullptr,
                                           tmp, nullptr, tmp, h1,
                                           lnw2, lnb2, a2,
                                           red + 2, nullptr, N);

    // ---- layer 3 ----
    aggregate128_kernel<<<aggGrid, 256>>>(tmp, rowptr, csr, inv, agg, N);
    gemm_sage<128, 128, 0><<<gemmGrid, 256>>>(agg, tmp, Wl3, Wr3, b3,
                                              out, nullptr, nullptr, nullptr,
                                              nullptr, nullptr, nullptr,
                                              nullptr, red + 4, N);
    ln_prelu_kernel<<<(int)(((long)N * 32 + 255) / 256), 256>>>(out, red + 4,
                                                                lnw3, lnb3, a3, N);
}